// round 2
// baseline (speedup 1.0000x reference)
#include <cuda_runtime.h>
#include <stdint.h>

#define NN 50000
#define NE 800000
#define DD 64

// scratch (no allocations allowed)
__device__ float g_agg[NN * DD];
__device__ float g_y0[NN * DD];

// ---------------------------------------------------------------------------
// zero the aggregation buffer (layer 0 only; layer 1's zeroing is folded
// into mlp kernel of layer 0)
// ---------------------------------------------------------------------------
__global__ void zero_agg_kernel() {
    int i = blockIdx.x * blockDim.x + threadIdx.x;
    if (i < NN * DD / 4) {
        ((float4*)g_agg)[i] = make_float4(0.f, 0.f, 0.f, 0.f);
    }
}

// ---------------------------------------------------------------------------
// edge scatter: agg[dst[e]] += X[src[e]]
// ---------------------------------------------------------------------------
__global__ void scatter_kernel(const float* __restrict__ xin, int in_scratch,
                               const int* __restrict__ src,
                               const int* __restrict__ dst) {
    const float* __restrict__ base = in_scratch ? g_y0 : xin;
    int t = blockIdx.x * blockDim.x + threadIdx.x;
    int e = t >> 4;
    if (e >= NE) return;
    int q = (t & 15) << 2;

    int s = src[e];
    int d = dst[e];

    float4 v = *(const float4*)(base + (size_t)s * DD + q);
    float* p = g_agg + (size_t)d * DD + q;
    asm volatile("red.global.add.v4.f32 [%0], {%1,%2,%3,%4};"
                 :: "l"(p), "f"(v.x), "f"(v.y), "f"(v.z), "f"(v.w)
                 : "memory");
}

// ---------------------------------------------------------------------------
// tensor-core MLP (3xTF32 split precision, mma.sync m16n8k8)
// block = 256 threads (8 warps), tile = 128 nodes x 64 cols, K = 64.
// warp w owns rows [16w, 16w+16) of the tile, all 64 output cols.
// ---------------------------------------------------------------------------
__device__ __forceinline__ float fast_tanh(float x) {
    float y;
    asm("tanh.approx.f32 %0, %1;" : "=f"(y) : "f"(x));
    return y;
}

__device__ __forceinline__ uint32_t f2tf32(float x) {
    uint32_t u;
    asm("cvt.rna.tf32.f32 %0, %1;" : "=r"(u) : "f"(x));
    return u;
}

__device__ __forceinline__ void split_tf32(float x, uint32_t& hi, uint32_t& lo) {
    hi = f2tf32(x);
    lo = f2tf32(x - __uint_as_float(hi));
}

__device__ __forceinline__ void mma_tf32(float* c, const uint32_t* a,
                                         const uint32_t* b) {
    asm volatile(
        "mma.sync.aligned.m16n8k8.row.col.f32.tf32.tf32.f32 "
        "{%0,%1,%2,%3},{%4,%5,%6,%7},{%8,%9},{%0,%1,%2,%3};"
        : "+f"(c[0]), "+f"(c[1]), "+f"(c[2]), "+f"(c[3])
        : "r"(a[0]), "r"(a[1]), "r"(a[2]), "r"(a[3]), "r"(b[0]), "r"(b[1]));
}

// smem (floats): sAh[8192] sAl[8192] sWh[4096] sWl[4096]  = 96 KB
#define S_AH 0
#define S_AL 8192
#define S_WH 16384
#define S_WL 20480
#define SMEM_FLOATS 24576

// A fragment-order offset for element (mtile, r16, k):
//   lane = (r16&7)*4 + (k8&3), reg = (r16>>3) + 2*(k8>>2)
// W fragment-order offset for element (k, n):
//   lane = n8*4 + (k8&3), reg = k8>>2

__device__ __forceinline__ void load_w_frags(const float* __restrict__ w,
                                             float* sWh, float* sWl, int tid) {
    #pragma unroll
    for (int i = 0; i < 16; i++) {
        int id = i * 256 + tid;       // 4096 elements
        int k = id >> 6, n = id & 63;
        float v = w[id];
        uint32_t hi, lo;
        split_tf32(v, hi, lo);
        int kt = k >> 3, k8 = k & 7, nt = n >> 3, n8 = n & 7;
        int off = ((kt * 8 + nt) * 32 + (n8 * 4 + (k8 & 3))) * 2 + (k8 >> 2);
        sWh[off] = __uint_as_float(hi);
        sWl[off] = __uint_as_float(lo);
    }
}

__global__ void __launch_bounds__(256)
mlp_mma_kernel(const float* __restrict__ xin, int in_scratch,
               const float* __restrict__ w1, const float* __restrict__ b1,
               const float* __restrict__ w2, const float* __restrict__ b2,
               float* __restrict__ out, int out_scratch, int clear_agg) {
    extern __shared__ float sm[];
    float* sAh = sm + S_AH;
    float* sAl = sm + S_AL;
    float* sWh = sm + S_WH;
    float* sWl = sm + S_WL;

    const float* __restrict__ xi = in_scratch ? g_y0 : xin;
    float* __restrict__ o = out_scratch ? g_y0 : out;

    const int tid = threadIdx.x;
    const int lane = tid & 31;
    const int w = tid >> 5;         // warp id 0..7
    const int n0 = blockIdx.x * 128;

    // ---- stage W1 fragments ----
    load_w_frags(w1, sWh, sWl, tid);

    // ---- stage A = x + agg fragments (hi/lo) ----
    #pragma unroll
    for (int i = 0; i < 8; i++) {
        int id = i * 256 + tid;     // float4 id over 128x64 tile (2048)
        int r = id >> 4;
        int kb = (id & 15) << 2;
        int row = n0 + r;
        float4 v;
        if (row < NN) {
            float4 a = *(const float4*)(xi + (size_t)row * DD + kb);
            float4 g = *(const float4*)(g_agg + (size_t)row * DD + kb);
            v = make_float4(a.x + g.x, a.y + g.y, a.z + g.z, a.w + g.w);
            if (clear_agg)
                *(float4*)(g_agg + (size_t)row * DD + kb) =
                    make_float4(0.f, 0.f, 0.f, 0.f);
        } else {
            v = make_float4(0.f, 0.f, 0.f, 0.f);
        }
        int mt = r >> 4;
        int r16 = r & 15;
        float vv[4] = {v.x, v.y, v.z, v.w};
        #pragma unroll
        for (int q = 0; q < 4; q++) {
            int k = kb + q;
            int kt = k >> 3, k8 = k & 7;
            int off = ((mt * 8 + kt) * 32 + ((r16 & 7) * 4 + (k8 & 3))) * 4 +
                      ((r16 >> 3) + 2 * (k8 >> 2));
            uint32_t hi, lo;
            split_tf32(vv[q], hi, lo);
            sAh[off] = __uint_as_float(hi);
            sAl[off] = __uint_as_float(lo);
        }
    }
    __syncthreads();

    float acc[8][4];

    // ---- GEMM1: h = A @ W1 + b1 ----
    #pragma unroll
    for (int nt = 0; nt < 8; nt++) {
        float bb0 = __ldg(b1 + nt * 8 + 2 * (lane & 3));
        float bb1 = __ldg(b1 + nt * 8 + 2 * (lane & 3) + 1);
        acc[nt][0] = bb0; acc[nt][1] = bb1;
        acc[nt][2] = bb0; acc[nt][3] = bb1;
    }
    #pragma unroll
    for (int kt = 0; kt < 8; kt++) {
        int abase = ((w * 8 + kt) * 32 + lane) * 4;
        uint4 ah4 = *(const uint4*)(sAh + abase);
        uint4 al4 = *(const uint4*)(sAl + abase);
        uint32_t ah[4] = {ah4.x, ah4.y, ah4.z, ah4.w};
        uint32_t al[4] = {al4.x, al4.y, al4.z, al4.w};
        #pragma unroll
        for (int nt = 0; nt < 8; nt++) {
            int bbase = ((kt * 8 + nt) * 32 + lane) * 2;
            uint2 bh2 = *(const uint2*)(sWh + bbase);
            uint2 bl2 = *(const uint2*)(sWl + bbase);
            uint32_t bh[2] = {bh2.x, bh2.y};
            uint32_t bl[2] = {bl2.x, bl2.y};
            mma_tf32(acc[nt], ah, bh);
            mma_tf32(acc[nt], al, bh);
            mma_tf32(acc[nt], ah, bl);
        }
    }

    // ---- tanh ----
    #pragma unroll
    for (int nt = 0; nt < 8; nt++)
        #pragma unroll
        for (int j = 0; j < 4; j++)
            acc[nt][j] = fast_tanh(acc[nt][j]);

    // all warps done reading W1 before overwrite
    __syncthreads();

    // ---- stage H fragments (warp-private region of sA) + W2 fragments ----
    #pragma unroll
    for (int nt = 0; nt < 8; nt++) {
        #pragma unroll
        for (int j = 0; j < 4; j++) {
            int r16 = (lane >> 2) + (j >> 1) * 8;
            int k = nt * 8 + 2 * (lane & 3) + (j & 1);
            int kt = k >> 3, k8 = k & 7;
            int off = ((w * 8 + kt) * 32 + ((r16 & 7) * 4 + (k8 & 3))) * 4 +
                      ((r16 >> 3) + 2 * (k8 >> 2));
            uint32_t hi, lo;
            split_tf32(acc[nt][j], hi, lo);
            sAh[off] = __uint_as_float(hi);
            sAl[off] = __uint_as_float(lo);
        }
    }
    load_w_frags(w2, sWh, sWl, tid);
    __syncthreads();

    // ---- GEMM2: y = H @ W2 + b2 ----
    #pragma unroll
    for (int nt = 0; nt < 8; nt++) {
        float bb0 = __ldg(b2 + nt * 8 + 2 * (lane & 3));
        float bb1 = __ldg(b2 + nt * 8 + 2 * (lane & 3) + 1);
        acc[nt][0] = bb0; acc[nt][1] = bb1;
        acc[nt][2] = bb0; acc[nt][3] = bb1;
    }
    #pragma unroll
    for (int kt = 0; kt < 8; kt++) {
        int abase = ((w * 8 + kt) * 32 + lane) * 4;
        uint4 ah4 = *(const uint4*)(sAh + abase);
        uint4 al4 = *(const uint4*)(sAl + abase);
        uint32_t ah[4] = {ah4.x, ah4.y, ah4.z, ah4.w};
        uint32_t al[4] = {al4.x, al4.y, al4.z, al4.w};
        #pragma unroll
        for (int nt = 0; nt < 8; nt++) {
            int bbase = ((kt * 8 + nt) * 32 + lane) * 2;
            uint2 bh2 = *(const uint2*)(sWh + bbase);
            uint2 bl2 = *(const uint2*)(sWl + bbase);
            uint32_t bh[2] = {bh2.x, bh2.y};
            uint32_t bl[2] = {bl2.x, bl2.y};
            mma_tf32(acc[nt], ah, bh);
            mma_tf32(acc[nt], al, bh);
            mma_tf32(acc[nt], ah, bl);
        }
    }

    // ---- store ----
    int r0 = n0 + w * 16 + (lane >> 2);
    int r1 = r0 + 8;
    #pragma unroll
    for (int nt = 0; nt < 8; nt++) {
        int col = nt * 8 + 2 * (lane & 3);
        if (r0 < NN)
            *(float2*)(o + (size_t)r0 * DD + col) =
                make_float2(acc[nt][0], acc[nt][1]);
        if (r1 < NN)
            *(float2*)(o + (size_t)r1 * DD + col) =
                make_float2(acc[nt][2], acc[nt][3]);
    }
}

// ---------------------------------------------------------------------------
// launch
// ---------------------------------------------------------------------------
extern "C" void kernel_launch(void* const* d_in, const int* in_sizes, int n_in,
                              void* d_out, int out_size) {
    const float* x    = (const float*)d_in[0];
    const int*   src  = (const int*)d_in[1];
    const int*   dst  = (const int*)d_in[2];
    const float* w1_0 = (const float*)d_in[3];
    const float* b1_0 = (const float*)d_in[4];
    const float* w2_0 = (const float*)d_in[5];
    const float* b2_0 = (const float*)d_in[6];
    const float* w1_1 = (const float*)d_in[7];
    const float* b1_1 = (const float*)d_in[8];
    const float* w2_1 = (const float*)d_in[9];
    const float* b2_1 = (const float*)d_in[10];
    float* out = (float*)d_out;

    const int smem_bytes = SMEM_FLOATS * sizeof(float);  // 96 KB
    static int configured = 0;
    cudaFuncSetAttribute(mlp_mma_kernel,
                         cudaFuncAttributeMaxDynamicSharedMemorySize, smem_bytes);
    (void)configured;

    const int zero_blocks = (NN * DD / 4 + 255) / 256;
    const int scat_blocks = (NE * 16 + 255) / 256;
    const int mlp_blocks  = (NN + 127) / 128;  // 391

    // ---- layer 0 ----
    zero_agg_kernel<<<zero_blocks, 256>>>();
    scatter_kernel<<<scat_blocks, 256>>>(x, 0, src, dst);
    mlp_mma_kernel<<<mlp_blocks, 256, smem_bytes>>>(
        x, 0, w1_0, b1_0, w2_0, b2_0, out, /*out_scratch=*/1, /*clear_agg=*/1);

    // ---- layer 1 ----
    scatter_kernel<<<scat_blocks, 256>>>(nullptr, 1, src, dst);
    mlp_mma_kernel<<<mlp_blocks, 256, smem_bytes>>>(
        nullptr, 1, w1_1, b1_1, w2_1, b2_1, out, /*out_scratch=*/0, /*clear_agg=*/0);
}

// round 4
// speedup vs baseline: 1.3161x; 1.3161x over previous
#include <cuda_runtime.h>
#include <stdint.h>

#define NN 50000
#define NE 800000
#define DD 64

#define SCAN_CHUNK 1024
#define NCHUNK ((NN + SCAN_CHUNK - 1) / SCAN_CHUNK)  // 49

// scratch (no allocations allowed)
__device__ float g_agg[NN * DD];     // holds h_in = x + sum(neighbors)
__device__ float g_y0[NN * DD];      // layer-0 output
__device__ int   g_cnt[NN];          // degree histogram, then fill cursor
__device__ int   g_rowptr[NN + 1];
__device__ int   g_col[NE];
__device__ int   g_partials[NCHUNK];

// ---------------------------------------------------------------------------
// CSR build
// ---------------------------------------------------------------------------
__global__ void zero_cnt_kernel() {
    int i = blockIdx.x * blockDim.x + threadIdx.x;
    if (i < NN) g_cnt[i] = 0;
    if (i == 0) g_rowptr[0] = 0;
}

__global__ void hist_kernel(const int* __restrict__ dst) {
    int e = blockIdx.x * blockDim.x + threadIdx.x;
    if (e < NE) atomicAdd(&g_cnt[dst[e]], 1);
}

// per-chunk inclusive scan -> rowptr[i+1], chunk totals -> g_partials
__global__ void scan1_kernel() {
    __shared__ int s[SCAN_CHUNK];
    int t = threadIdx.x;
    int i = blockIdx.x * SCAN_CHUNK + t;
    int v = (i < NN) ? g_cnt[i] : 0;
    s[t] = v;
    __syncthreads();
    #pragma unroll
    for (int off = 1; off < SCAN_CHUNK; off <<= 1) {
        int add = (t >= off) ? s[t - off] : 0;
        __syncthreads();
        s[t] += add;
        __syncthreads();
    }
    if (i < NN) g_rowptr[i + 1] = s[t];
    if (t == SCAN_CHUNK - 1) g_partials[blockIdx.x] = s[t];
}

// exclusive scan of chunk totals (tiny)
__global__ void scan2_kernel() {
    if (threadIdx.x == 0) {
        int run = 0;
        for (int c = 0; c < NCHUNK; c++) {
            int v = g_partials[c];
            g_partials[c] = run;
            run += v;
        }
    }
}

// add chunk offsets, reset cursors
__global__ void scan3_kernel() {
    int i = blockIdx.x * blockDim.x + threadIdx.x;
    if (i < NN) {
        g_rowptr[i + 1] += g_partials[i >> 10];
        g_cnt[i] = 0;
    }
}

__global__ void fill_kernel(const int* __restrict__ src,
                            const int* __restrict__ dst) {
    int e = blockIdx.x * blockDim.x + threadIdx.x;
    if (e < NE) {
        int d = dst[e];
        int pos = atomicAdd(&g_cnt[d], 1);
        g_col[g_rowptr[d] + pos] = src[e];
    }
}

// ---------------------------------------------------------------------------
// aggregation gather: g_agg[n] = X[n] + sum_{j in N_in(n)} X[j]
// X = xin (layer 0) or g_y0 (layer 1), selected by flag IN DEVICE CODE.
// half-warp (16 lanes) per node, one float4 per lane.
// ---------------------------------------------------------------------------
__global__ void __launch_bounds__(256)
gather_kernel(const float* __restrict__ xin, int in_scratch) {
    const float* __restrict__ base = in_scratch ? g_y0 : xin;
    int t = blockIdx.x * blockDim.x + threadIdx.x;
    int node = t >> 4;            // 16 threads per node
    if (node >= NN) return;
    int col = (t & 15) << 2;      // float offset

    float4 acc = *(const float4*)(base + (size_t)node * DD + col);

    int p   = g_rowptr[node];
    int end = g_rowptr[node + 1];

    // 2-wide unrolled neighbor loop for memory-level parallelism
    for (; p + 1 < end; p += 2) {
        int j0 = g_col[p];
        int j1 = g_col[p + 1];
        float4 a = *(const float4*)(base + (size_t)j0 * DD + col);
        float4 b = *(const float4*)(base + (size_t)j1 * DD + col);
        acc.x += a.x + b.x;
        acc.y += a.y + b.y;
        acc.z += a.z + b.z;
        acc.w += a.w + b.w;
    }
    if (p < end) {
        int j0 = g_col[p];
        float4 a = *(const float4*)(base + (size_t)j0 * DD + col);
        acc.x += a.x; acc.y += a.y; acc.z += a.z; acc.w += a.w;
    }

    *(float4*)(g_agg + (size_t)node * DD + col) = acc;
}

// ---------------------------------------------------------------------------
// fused MLP for one GIN layer: out = tanh(g_agg @ W1 + b1) @ W2 + b2
// ---------------------------------------------------------------------------
__device__ __forceinline__ float fast_tanh(float x) {
    float y;
    asm("tanh.approx.f32 %0, %1;" : "=f"(y) : "f"(x));
    return y;
}

#define T_STRIDE 65

__global__ void __launch_bounds__(128, 2)
mlp_kernel(const float* __restrict__ w1, const float* __restrict__ b1,
           const float* __restrict__ w2, const float* __restrict__ b2,
           float* __restrict__ out, int out_scratch) {
    extern __shared__ float sm[];
    float* sW1 = sm;                    // 64*64
    float* sW2 = sm + 4096;             // 64*64
    float* sT  = sm + 8192;             // 64 * T_STRIDE
    float* sH  = sT + 64 * T_STRIDE;    // 64 * T_STRIDE

    float* __restrict__ o = out_scratch ? g_y0 : out;

    const int tid = threadIdx.x;
    const int n0 = blockIdx.x * 64;

    // ---- load weights into smem (coalesced float4) ----
    #pragma unroll
    for (int rep = 0; rep < 8; rep++) {
        int f4 = rep * 128 + tid;
        ((float4*)sW1)[f4] = ((const float4*)w1)[f4];
        ((float4*)sW2)[f4] = ((const float4*)w2)[f4];
    }

    // ---- load node tile into sT ----
    #pragma unroll
    for (int rep = 0; rep < 8; rep++) {
        int f4 = rep * 128 + tid;
        int n = f4 >> 4;
        int k = (f4 & 15) << 2;
        float4 v;
        if (n0 + n < NN) {
            v = *(const float4*)(g_agg + (size_t)(n0 + n) * DD + k);
        } else {
            v = make_float4(0.f, 0.f, 0.f, 0.f);
        }
        float* p = sT + n * T_STRIDE + k;
        p[0] = v.x; p[1] = v.y; p[2] = v.z; p[3] = v.w;
    }
    __syncthreads();

    const int ng = tid & 15;
    const int cg = tid >> 4;
    const int nb = ng * 4;
    const int cb = cg * 8;

    float acc[4][8];

    // ---- GEMM1 ----
    {
        float bv[8];
        #pragma unroll
        for (int u = 0; u < 8; u++) bv[u] = b1[cb + u];
        #pragma unroll
        for (int j = 0; j < 4; j++)
            #pragma unroll
            for (int u = 0; u < 8; u++) acc[j][u] = bv[u];

        #pragma unroll 4
        for (int k = 0; k < 64; k++) {
            float4 wA = *(const float4*)(sW1 + k * 64 + cb);
            float4 wB = *(const float4*)(sW1 + k * 64 + cb + 4);
            float w[8] = {wA.x, wA.y, wA.z, wA.w, wB.x, wB.y, wB.z, wB.w};
            #pragma unroll
            for (int j = 0; j < 4; j++) {
                float tv = sT[(nb + j) * T_STRIDE + k];
                #pragma unroll
                for (int u = 0; u < 8; u++) acc[j][u] += tv * w[u];
            }
        }
    }

    // ---- tanh + stage h ----
    #pragma unroll
    for (int j = 0; j < 4; j++)
        #pragma unroll
        for (int u = 0; u < 8; u++)
            sH[(nb + j) * T_STRIDE + cb + u] = fast_tanh(acc[j][u]);
    __syncthreads();

    // ---- GEMM2 ----
    {
        float bv[8];
        #pragma unroll
        for (int u = 0; u < 8; u++) bv[u] = b2[cb + u];
        #pragma unroll
        for (int j = 0; j < 4; j++)
            #pragma unroll
            for (int u = 0; u < 8; u++) acc[j][u] = bv[u];

        #pragma unroll 4
        for (int k = 0; k < 64; k++) {
            float4 wA = *(const float4*)(sW2 + k * 64 + cb);
            float4 wB = *(const float4*)(sW2 + k * 64 + cb + 4);
            float w[8] = {wA.x, wA.y, wA.z, wA.w, wB.x, wB.y, wB.z, wB.w};
            #pragma unroll
            for (int j = 0; j < 4; j++) {
                float hv = sH[(nb + j) * T_STRIDE + k];
                #pragma unroll
                for (int u = 0; u < 8; u++) acc[j][u] += hv * w[u];
            }
        }
    }

    // ---- store ----
    #pragma unroll
    for (int j = 0; j < 4; j++) {
        int n = n0 + nb + j;
        if (n < NN) {
            float4 o1 = make_float4(acc[j][0], acc[j][1], acc[j][2], acc[j][3]);
            float4 o2 = make_float4(acc[j][4], acc[j][5], acc[j][6], acc[j][7]);
            *(float4*)(o + (size_t)n * DD + cb) = o1;
            *(float4*)(o + (size_t)n * DD + cb + 4) = o2;
        }
    }
}

// ---------------------------------------------------------------------------
// launch
// ---------------------------------------------------------------------------
extern "C" void kernel_launch(void* const* d_in, const int* in_sizes, int n_in,
                              void* d_out, int out_size) {
    const float* x    = (const float*)d_in[0];
    const int*   src  = (const int*)d_in[1];
    const int*   dst  = (const int*)d_in[2];
    const float* w1_0 = (const float*)d_in[3];
    const float* b1_0 = (const float*)d_in[4];
    const float* w2_0 = (const float*)d_in[5];
    const float* b2_0 = (const float*)d_in[6];
    const float* w1_1 = (const float*)d_in[7];
    const float* b1_1 = (const float*)d_in[8];
    const float* w2_1 = (const float*)d_in[9];
    const float* b2_1 = (const float*)d_in[10];
    float* out = (float*)d_out;

    const int smem_bytes = (4096 * 2 + 64 * T_STRIDE * 2) * sizeof(float);
    cudaFuncSetAttribute(mlp_kernel, cudaFuncAttributeMaxDynamicSharedMemorySize,
                         smem_bytes);

    const int nodeb  = (NN + 255) / 256;
    const int edgeb  = (NE + 255) / 256;
    const int gathb  = (NN * 16 + 255) / 256;
    const int mlpb   = (NN + 63) / 64;

    // ---- CSR build (once, reused by both layers) ----
    zero_cnt_kernel<<<nodeb, 256>>>();
    hist_kernel<<<edgeb, 256>>>(dst);
    scan1_kernel<<<NCHUNK, SCAN_CHUNK>>>();
    scan2_kernel<<<1, 32>>>();
    scan3_kernel<<<nodeb, 256>>>();
    fill_kernel<<<edgeb, 256>>>(src, dst);

    // ---- layer 0 ----
    gather_kernel<<<gathb, 256>>>(x, /*in_scratch=*/0);
    mlp_kernel<<<mlpb, 128, smem_bytes>>>(w1_0, b1_0, w2_0, b2_0,
                                          out, /*out_scratch=*/1);

    // ---- layer 1 ----
    gather_kernel<<<gathb, 256>>>(nullptr, /*in_scratch=*/1);
    mlp_kernel<<<mlpb, 128, smem_bytes>>>(w1_1, b1_1, w2_1, b2_1,
                                          out, /*out_scratch=*/0);
}